// round 6
// baseline (speedup 1.0000x reference)
#include <cuda_runtime.h>
#include <cstdint>
#include <cstddef>

#define FULLMASK 0xFFFFFFFFu

// ---------------- problem constants ------------------------------------------
constexpr int B  = 32;
constexpr int H  = 768;
constexpr int KQ = 131072;

// ---------------- mma.sync matmul tiling --------------------------------------
constexpr int MROWS = 128;            // queue rows per CTA (1024 CTAs)
constexpr int CH    = 64;             // K-chunk in fp32 elems (32 bf16x2 words)
constexpr int NCHT  = H / CH;         // 12
constexpr int TCTHREADS = 128;        // 4 warps; warp w owns rows [32w,32w+32)
constexpr int AST   = 36;             // A smem stride in words (32 + 4 pad)
// smem layout (bytes)
constexpr int SM_A     = 0;                      // hi: 128*36*4=18432, lo: +18432
constexpr int SM_B     = 36864;                  // hi: 32*36*4=4608,  lo: +4608
constexpr int SM_CLB   = 46080;                  // 32 ints
constexpr int SM_LBB   = 46208;                  // 32 ints
constexpr int SMEM_TC  = 46336;
// epilogue reuse (inside A region):
constexpr int SM_SIMS  = 0;                      // 128*33 floats = 16896
constexpr int SM_STAGE = 16896;                  // 4096 uints = 16384
constexpr int SM_WC    = 33280;                  // 256 ints
constexpr int SM_LOFS  = 34304;                  // 64 ints
constexpr int SM_BASE  = 34560;                  // 64 ints
constexpr int SM_CNT   = 34816;                  // 64 ints

// ---------------- scratch ----------------------------------------------------
__device__ unsigned int g_bufP [(size_t)B * KQ];
__device__ unsigned int g_bufN0[(size_t)B * KQ];
__device__ unsigned int g_bufN1[(size_t)B * KQ];
__device__ unsigned int g_histA[B * 8192];
__device__ int g_cntP[B];
__device__ int g_cntN[B];
__device__ int g_pmm[2];
__device__ unsigned int g_posPart[B * 16 * 10];
__device__ unsigned int g_posTop[B * 16];
__device__ unsigned int g_qhi[B * H / 2];     // bf16x2 words, [32][384]
__device__ unsigned int g_qlo[B * H / 2];

__device__ __forceinline__ unsigned int keyOf(float f) {
    unsigned int u = __float_as_uint(f);
    return (u & 0x80000000u) ? u : (~u & 0x7FFFFFFFu);
}
__device__ __forceinline__ float valOf(unsigned int d) {
    unsigned int u = (d & 0x80000000u) ? d : (~d & 0x7FFFFFFFu);
    return __uint_as_float(u);
}

#define CVT_BF16X2(res, e0, e1) \
    asm("cvt.rn.satfinite.bf16x2.f32 %0, %1, %2;" : "=r"(res) : "f"(e1), "f"(e0))

// mma.sync bf16: D(16x8,f32) += A(16x16) * B(16x8)
__device__ __forceinline__ void mma_bf16(float* d, const unsigned* a, const unsigned* b) {
    asm volatile("mma.sync.aligned.m16n8k16.row.col.f32.bf16.bf16.f32 "
                 "{%0,%1,%2,%3}, {%4,%5,%6,%7}, {%8,%9}, {%0,%1,%2,%3};"
                 : "+f"(d[0]), "+f"(d[1]), "+f"(d[2]), "+f"(d[3])
                 : "r"(a[0]), "r"(a[1]), "r"(a[2]), "r"(a[3]),
                   "r"(b[0]), "r"(b[1]));
}

// ---------------- kernel 0: zero counters -------------------------------------
__global__ void zero_k() {
    int t = threadIdx.x;
    if (t < B) { g_cntP[t] = 0; g_cntN[t] = 0; }
}

// ---------------- kernel: split queries into bf16 hi/lo ------------------------
__global__ void prep_q(const float* __restrict__ q) {
    int w = blockIdx.x * 256 + threadIdx.x;
    if (w >= B * H / 2) return;
    float x0 = q[2 * w], x1 = q[2 * w + 1];
    unsigned int whi; CVT_BF16X2(whi, x0, x1);
    float h0 = __uint_as_float(whi << 16);
    float h1 = __uint_as_float(whi & 0xFFFF0000u);
    unsigned int wlo; CVT_BF16X2(wlo, x0 - h0, x1 - h1);
    g_qhi[w] = whi;
    g_qlo[w] = wlo;
}

// ---------------- kernel 1: mma.sync matmul + mask partition -------------------
__global__ __launch_bounds__(TCTHREADS, 2)
void mm_tc(const float* __restrict__ fq,
           const int* __restrict__ lab_q, const int* __restrict__ clu_q,
           const int* __restrict__ lab_k, const int* __restrict__ clu_k)
{
    extern __shared__ char sm[];
    const int t = threadIdx.x;
    const int w = t >> 5, lane = t & 31;
    const int g = lane >> 2, c4 = lane & 3;
    const int k0 = blockIdx.x * MROWS;

    int* s_clb = (int*)(sm + SM_CLB);
    int* s_lbb = (int*)(sm + SM_LBB);
    if (t < 32) { s_clb[t] = clu_q[t]; s_lbb[t] = lab_q[t]; }

    unsigned int* smAh = (unsigned int*)(sm + SM_A);
    unsigned int* smAl = smAh + MROWS * AST;         // 4608 words
    unsigned int* smBh = (unsigned int*)(sm + SM_B);
    unsigned int* smBl = smBh + 32 * AST;            // 1152 words

    const float4* gA = (const float4*)(fq + (size_t)(k0 + t) * H);

    float4 areg[16];
    unsigned int bhr[8], blr[8];

    auto loadChunk = [&](int c) {
        const float4* p = gA + c * 16;
        #pragma unroll
        for (int ii = 0; ii < 16; ii++) areg[ii] = p[ii];
        #pragma unroll
        for (int ps = 0; ps < 8; ps++) {
            int idx = ps * TCTHREADS + t;
            int n = idx >> 5, wd = idx & 31;
            bhr[ps] = g_qhi[n * (H / 2) + c * 32 + wd];
            blr[ps] = g_qlo[n * (H / 2) + c * 32 + wd];
        }
    };
    auto storeChunk = [&]() {
        #pragma unroll
        for (int ii = 0; ii < 16; ii += 2) {
            float4 v0 = areg[ii], v1 = areg[ii + 1];
            unsigned int h0, h1, h2, h3, l0, l1, l2, l3;
            CVT_BF16X2(h0, v0.x, v0.y);
            CVT_BF16X2(h1, v0.z, v0.w);
            CVT_BF16X2(h2, v1.x, v1.y);
            CVT_BF16X2(h3, v1.z, v1.w);
            float r0 = v0.x - __uint_as_float(h0 << 16);
            float r1 = v0.y - __uint_as_float(h0 & 0xFFFF0000u);
            float r2 = v0.z - __uint_as_float(h1 << 16);
            float r3 = v0.w - __uint_as_float(h1 & 0xFFFF0000u);
            float r4 = v1.x - __uint_as_float(h2 << 16);
            float r5 = v1.y - __uint_as_float(h2 & 0xFFFF0000u);
            float r6 = v1.z - __uint_as_float(h3 << 16);
            float r7 = v1.w - __uint_as_float(h3 & 0xFFFF0000u);
            CVT_BF16X2(l0, r0, r1);
            CVT_BF16X2(l1, r2, r3);
            CVT_BF16X2(l2, r4, r5);
            CVT_BF16X2(l3, r6, r7);
            *(uint4*)&smAh[t * AST + 2 * ii] = make_uint4(h0, h1, h2, h3);
            *(uint4*)&smAl[t * AST + 2 * ii] = make_uint4(l0, l1, l2, l3);
        }
        #pragma unroll
        for (int ps = 0; ps < 8; ps++) {
            int idx = ps * TCTHREADS + t;
            int n = idx >> 5, wd = idx & 31;
            smBh[n * AST + wd] = bhr[ps];
            smBl[n * AST + wd] = blr[ps];
        }
    };

    float acc[2][4][4];
    #pragma unroll
    for (int mt = 0; mt < 2; mt++)
        #pragma unroll
        for (int nt = 0; nt < 4; nt++)
            #pragma unroll
            for (int r = 0; r < 4; r++) acc[mt][nt][r] = 0.0f;

    loadChunk(0);
    for (int c = 0; c < NCHT; c++) {
        if (c > 0) __syncthreads();    // everyone done reading smem before overwrite
        storeChunk();
        if (c + 1 < NCHT) loadChunk(c + 1);
        __syncthreads();

        #pragma unroll
        for (int ks = 0; ks < 4; ks++) {
            const int kw = ks * 8 + c4;
            unsigned int ah[2][4], al[2][4], bh[4][2], bl[4][2];
            #pragma unroll
            for (int mt = 0; mt < 2; mt++) {
                int r0 = (w * 32 + mt * 16 + g) * AST;
                int r1 = r0 + 8 * AST;
                ah[mt][0] = smAh[r0 + kw];     ah[mt][1] = smAh[r1 + kw];
                ah[mt][2] = smAh[r0 + kw + 4]; ah[mt][3] = smAh[r1 + kw + 4];
                al[mt][0] = smAl[r0 + kw];     al[mt][1] = smAl[r1 + kw];
                al[mt][2] = smAl[r0 + kw + 4]; al[mt][3] = smAl[r1 + kw + 4];
            }
            #pragma unroll
            for (int nt = 0; nt < 4; nt++) {
                int nb = (nt * 8 + g) * AST;
                bh[nt][0] = smBh[nb + kw]; bh[nt][1] = smBh[nb + kw + 4];
                bl[nt][0] = smBl[nb + kw]; bl[nt][1] = smBl[nb + kw + 4];
            }
            #pragma unroll
            for (int mt = 0; mt < 2; mt++)
                #pragma unroll
                for (int nt = 0; nt < 4; nt++)
                    mma_bf16(acc[mt][nt], ah[mt], bh[nt]);
            #pragma unroll
            for (int mt = 0; mt < 2; mt++)
                #pragma unroll
                for (int nt = 0; nt < 4; nt++)
                    mma_bf16(acc[mt][nt], ah[mt], bl[nt]);
            #pragma unroll
            for (int mt = 0; mt < 2; mt++)
                #pragma unroll
                for (int nt = 0; nt < 4; nt++)
                    mma_bf16(acc[mt][nt], al[mt], bh[nt]);
        }
    }
    __syncthreads();

    // ---- write sims fragments to smem [row][33] ------------------------------
    float* sims = (float*)(sm + SM_SIMS);
    #pragma unroll
    for (int mt = 0; mt < 2; mt++) {
        int r0 = w * 32 + mt * 16 + g;
        #pragma unroll
        for (int nt = 0; nt < 4; nt++) {
            int cb = nt * 8 + 2 * c4;
            sims[r0 * 33 + cb]           = acc[mt][nt][0];
            sims[r0 * 33 + cb + 1]       = acc[mt][nt][1];
            sims[(r0 + 8) * 33 + cb]     = acc[mt][nt][2];
            sims[(r0 + 8) * 33 + cb + 1] = acc[mt][nt][3];
        }
    }
    __syncthreads();

    // ---- epilogue: one thread per queue row ----------------------------------
    unsigned int* stage = (unsigned int*)(sm + SM_STAGE);
    int* s_wc   = (int*)(sm + SM_WC);     // [seg][warp 0..3]
    int* s_lofs = (int*)(sm + SM_LOFS);
    int* s_base = (int*)(sm + SM_BASE);
    int* s_cnt  = (int*)(sm + SM_CNT);

    int clk = clu_k[k0 + t];
    int lbk = lab_k[k0 + t];
    float myS[32];
    #pragma unroll
    for (int b = 0; b < 32; b++) myS[b] = sims[t * 33 + b];

    #pragma unroll
    for (int b = 0; b < 32; b++) {
        int neg = (clk == s_clb[b]) != (lbk == s_lbb[b]);
        unsigned int mask = __ballot_sync(FULLMASK, neg);
        if (lane == 0) {
            int cn = __popc(mask);
            s_wc[(b * 2 + 1) * 4 + w] = cn;
            s_wc[(b * 2) * 4 + w] = 32 - cn;
        }
    }
    __syncthreads();
    if (t < 64) {
        int run = 0, st[4];
        #pragma unroll
        for (int ww = 0; ww < 4; ww++) { st[ww] = run; run += s_wc[t * 4 + ww]; }
        #pragma unroll
        for (int ww = 0; ww < 4; ww++) s_wc[t * 4 + ww] = st[ww];
        s_cnt[t] = run;
        int b = t >> 1, neg = t & 1;
        s_base[t] = run ? atomicAdd(neg ? &g_cntN[b] : &g_cntP[b], run) : 0;
    }
    __syncthreads();
    if (t == 0) {
        int run = 0;
        for (int s = 0; s < 64; s++) { s_lofs[s] = run; run += s_cnt[s]; }
    }
    __syncthreads();
    {
        unsigned int below = (1u << lane) - 1u;
        #pragma unroll
        for (int b = 0; b < 32; b++) {
            int neg = (clk == s_clb[b]) != (lbk == s_lbb[b]);
            unsigned int mask = __ballot_sync(FULLMASK, neg);
            int seg = b * 2 + neg;
            int rank = neg ? __popc(mask & below) : __popc(~mask & below);
            stage[s_lofs[seg] + s_wc[seg * 4 + w] + rank] = keyOf(myS[b]);
        }
    }
    __syncthreads();
    // coalesced copy-out: warp w handles 16 segments
    for (int s = w * 16; s < w * 16 + 16; s++) {
        int cnt = s_cnt[s];
        int b = s >> 1, neg = s & 1;
        unsigned int* dst = (neg ? g_bufN0 : g_bufP) + (size_t)b * KQ + s_base[s];
        const unsigned int* srcP = stage + s_lofs[s];
        for (int i = lane; i < cnt; i += 32) dst[i] = srcP[i];
    }
}

// ---------------- kernel 2: pos_min / neg_min ---------------------------------
__global__ void minmax_k(const int* __restrict__ topk) {
    int t = threadIdx.x;
    int cp = g_cntP[t], cn = g_cntN[t];
    #pragma unroll
    for (int off = 16; off; off >>= 1) {
        cp = min(cp, __shfl_down_sync(FULLMASK, cp, off));
        cn = min(cn, __shfl_down_sync(FULLMASK, cn, off));
    }
    if (t == 0) { g_pmm[0] = min(cp, topk[0]); g_pmm[1] = cn; }
}

// ---------------- top-10 of positives -----------------------------------------
__device__ __forceinline__ void insert10(unsigned int (&best)[10], unsigned int k) {
    if (k < best[9]) {
        int j = 9;
        #pragma unroll
        for (int s = 0; s < 9; s++) {
            if (j > 0 && best[j - 1] > k) { best[j] = best[j - 1]; j--; }
        }
        best[j] = k;
    }
}

__global__ void pos_part() {
    int c = blockIdx.x, row = blockIdx.y;
    int n = g_cntP[row];
    int per = (n + 15) >> 4;
    int s = c * per, e = min(s + per, n);
    const unsigned int* src = g_bufP + (size_t)row * KQ;
    int t = threadIdx.x;
    int w = t >> 5, lane = t & 31;
    unsigned int best[10];
    #pragma unroll
    for (int i = 0; i < 10; i++) best[i] = 0xFFFFFFFFu;
    for (int base = s; base < e; base += 1024) {
        unsigned int k0 = (base + 0 * 256 + t < e) ? src[base + 0 * 256 + t] : 0xFFFFFFFFu;
        unsigned int k1 = (base + 1 * 256 + t < e) ? src[base + 1 * 256 + t] : 0xFFFFFFFFu;
        unsigned int k2 = (base + 2 * 256 + t < e) ? src[base + 2 * 256 + t] : 0xFFFFFFFFu;
        unsigned int k3 = (base + 3 * 256 + t < e) ? src[base + 3 * 256 + t] : 0xFFFFFFFFu;
        insert10(best, k0); insert10(best, k1); insert10(best, k2); insert10(best, k3);
    }
    // warp-level merge: 10 extract-min rounds, no barriers
    __shared__ unsigned int sh[8 * 10];
    #pragma unroll
    for (int r = 0; r < 10; r++) {
        unsigned int cand = best[0];
        unsigned int wmin = cand;
        #pragma unroll
        for (int off = 16; off; off >>= 1)
            wmin = min(wmin, __shfl_xor_sync(FULLMASK, wmin, off));
        unsigned int bal = __ballot_sync(FULLMASK, cand == wmin);
        int leader = __ffs(bal) - 1;
        if (lane == leader) {
            #pragma unroll
            for (int i = 0; i < 9; i++) best[i] = best[i + 1];
            best[9] = 0xFFFFFFFFu;
        }
        if (lane == 0) sh[w * 10 + r] = wmin;
    }
    __syncthreads();
    if (w == 0) {
        int head = 0;
        for (int r = 0; r < 10; r++) {
            unsigned int cand = (lane < 8) ? sh[lane * 10 + head] : 0xFFFFFFFFu;
            unsigned int wmin = cand;
            #pragma unroll
            for (int off = 16; off; off >>= 1)
                wmin = min(wmin, __shfl_xor_sync(FULLMASK, wmin, off));
            unsigned int bal = __ballot_sync(FULLMASK, cand == wmin && lane < 8);
            int leader = __ffs(bal) - 1;
            if (lane == leader) head++;
            if (lane == 0) g_posPart[(row * 16 + c) * 10 + r] = wmin;
        }
    }
}

__global__ void pos_merge() {
    int row = blockIdx.x;
    int lane = threadIdx.x;
    unsigned int v[5];
    #pragma unroll
    for (int j = 0; j < 5; j++) v[j] = g_posPart[row * 160 + lane * 5 + j];
    for (int i = 0; i < 10; i++) {
        unsigned int lmin = v[0];
        #pragma unroll
        for (int j = 1; j < 5; j++) lmin = min(lmin, v[j]);
        unsigned int wmin = lmin;
        #pragma unroll
        for (int off = 16; off; off >>= 1)
            wmin = min(wmin, __shfl_xor_sync(FULLMASK, wmin, off));
        unsigned int bal = __ballot_sync(FULLMASK, lmin == wmin);
        int leader = __ffs(bal) - 1;
        if (lane == leader) {
            bool done = false;
            #pragma unroll
            for (int j = 0; j < 5; j++) {
                if (!done && v[j] == wmin) { v[j] = 0xFFFFFFFFu; done = true; }
            }
        }
        if (lane == 0) g_posTop[row * 16 + i] = wmin;
    }
}

// ---------------- radix sort: 3x8-bit LSD over bits [8,32) --------------------
__global__ void rs_hist(int shift, int srcSel) {
    int chunk = blockIdx.x, row = blockIdx.y;
    int n = g_cntN[row];
    int s0 = chunk * 4096;
    __shared__ int h[256];
    int t = threadIdx.x;
    h[t] = 0;
    __syncthreads();
    if (s0 < n) {
        const unsigned int* in = (srcSel ? g_bufN1 : g_bufN0) + (size_t)row * KQ;
        int lim = min(4096, n - s0);
        for (int i = t; i < lim; i += 256)
            atomicAdd(&h[(in[s0 + i] >> shift) & 255], 1);
    }
    __syncthreads();
    g_histA[row * 8192 + t * 32 + chunk] = h[t];
}

__global__ void rs_scan() {
    int row = blockIdx.x;
    unsigned int* a = g_histA + row * 8192;
    int t = threadIdx.x;
    int v[32]; int sum = 0;
    int base = t * 32;
    #pragma unroll
    for (int i = 0; i < 32; i++) { v[i] = (int)a[base + i]; sum += v[i]; }
    __shared__ int ps[256];
    ps[t] = sum;
    __syncthreads();
    for (int off = 1; off < 256; off <<= 1) {
        int x = (t >= off) ? ps[t - off] : 0;
        __syncthreads();
        ps[t] += x;
        __syncthreads();
    }
    int run = (t > 0) ? ps[t - 1] : 0;
    #pragma unroll
    for (int i = 0; i < 32; i++) { int tmp = v[i]; a[base + i] = (unsigned)run; run += tmp; }
}

__global__ __launch_bounds__(256)
void rs_scatter(int shift, int srcSel) {
    int chunk = blockIdx.x, row = blockIdx.y;
    int n = g_cntN[row];
    int s0 = chunk * 4096;
    if (s0 >= n) return;
    const unsigned int* in  = (srcSel ? g_bufN1 : g_bufN0) + (size_t)row * KQ;
    unsigned int*       out = (srcSel ? g_bufN0 : g_bufN1) + (size_t)row * KQ;
    const unsigned int* Hb  = g_histA + row * 8192;

    __shared__ unsigned int sKeys[4096];
    __shared__ int wh[8 * 256];
    __shared__ int gb[256];
    __shared__ int lofs[256];
    __shared__ int ps[256];

    int t = threadIdx.x;
    int w = t >> 5, lane = t & 31;
    int wbase = s0 + 512 * w;

    unsigned int myKeys[16];
    #pragma unroll
    for (int j = 0; j < 16; j++) {
        int idx = wbase + 32 * j + lane;
        myKeys[j] = (idx < n) ? in[idx] : 0xFFFFFFFFu;
    }

    #pragma unroll
    for (int qq = 0; qq < 8; qq++) wh[qq * 256 + t] = 0;
    __syncthreads();

    #pragma unroll
    for (int j = 0; j < 16; j++) {
        int idx = wbase + 32 * j + lane;
        if (idx < n) atomicAdd(&wh[w * 256 + ((myKeys[j] >> shift) & 255)], 1);
    }
    __syncthreads();

    int tot = 0; int wstart[8];
    #pragma unroll
    for (int ww = 0; ww < 8; ww++) { wstart[ww] = tot; tot += wh[ww * 256 + t]; }
    ps[t] = tot;
    gb[t] = (int)Hb[t * 32 + chunk];
    __syncthreads();
    for (int off = 1; off < 256; off <<= 1) {
        int x = (t >= off) ? ps[t - off] : 0;
        __syncthreads();
        ps[t] += x;
        __syncthreads();
    }
    int lo = ps[t] - tot;
    lofs[t] = lo;
    #pragma unroll
    for (int ww = 0; ww < 8; ww++) wh[ww * 256 + t] = lo + wstart[ww];
    __syncthreads();

    #pragma unroll
    for (int j = 0; j < 16; j++) {
        int idx = wbase + 32 * j + lane;
        bool val = idx < n;
        unsigned int key = myKeys[j];
        int d = (key >> shift) & 255;
        unsigned int vm = __ballot_sync(FULLMASK, val);
        unsigned int peers = FULLMASK;
        #pragma unroll
        for (int bb = 0; bb < 8; ++bb) {
            unsigned int vote = __ballot_sync(FULLMASK, (d >> bb) & 1);
            peers &= ((d >> bb) & 1) ? vote : ~vote;
        }
        peers &= vm;
        int rank = __popc(peers & ((1u << lane) - 1u));
        int leader = peers ? (__ffs(peers) - 1) : 0;
        int basePos = 0;
        if (val && rank == 0) basePos = atomicAdd(&wh[w * 256 + d], __popc(peers));
        basePos = __shfl_sync(FULLMASK, basePos, leader);
        if (val) sKeys[basePos + rank] = key;
    }
    __syncthreads();

    int lim = min(4096, n - s0);
    for (int pos = t; pos < lim; pos += 256) {
        unsigned int key = sKeys[pos];
        int d = (key >> shift) & 255;
        out[gb[d] + (pos - lofs[d])] = key;
    }
}

// ---------------- writer (final sorted negatives in g_bufN1) -------------------
__global__ void write_k(float* __restrict__ out) {
    int r = blockIdx.y;
    unsigned int pm = (unsigned int)g_pmm[0];
    unsigned int nm = (unsigned int)g_pmm[1];
    if ((unsigned)r >= 32u * pm) return;
    unsigned int width = nm + 1u;
    unsigned int b = (unsigned)r / pm;
    unsigned int p = (unsigned)r - b * pm;
    const float invT = 1.0f / 0.07f;
    size_t rowBase = (size_t)r * width;
    const unsigned int* negRow = g_bufN1 + (size_t)b * KQ;

    unsigned int qlen = (width + 3u) >> 2;
    unsigned int c = blockIdx.x * qlen + threadIdx.x;
    unsigned int cend = min((blockIdx.x + 1u) * qlen, width);
    if (c >= cend) return;
    if (c == 0u) {
        out[rowBase] = valOf(g_posTop[b * 16 + p]) * invT;
        c += 256u;
        if (c >= cend) return;
    }
    unsigned int num = p * nm + (c - 1u);
    unsigned int qi = num / pm;
    unsigned int rem = num - qi * pm;
    unsigned int d256 = 256u / pm;
    unsigned int r256 = 256u - d256 * pm;
    while (c < cend) {
        out[rowBase + c] = valOf(negRow[qi]) * invT;
        c += 256u;
        qi += d256;
        rem += r256;
        if (rem >= pm) { rem -= pm; qi += 1u; }
    }
}

// ---------------- launcher ----------------------------------------------------
extern "C" void kernel_launch(void* const* d_in, const int* in_sizes, int n_in,
                              void* d_out, int out_size) {
    const float* q     = (const float*)d_in[0];
    const float* fq    = (const float*)d_in[1];
    const int* lab_q   = (const int*)d_in[2];
    const int* clu_q   = (const int*)d_in[3];
    const int* lab_k   = (const int*)d_in[4];
    const int* clu_k   = (const int*)d_in[5];
    const int* topk    = (const int*)d_in[6];
    float* out = (float*)d_out;

    zero_k<<<1, 32>>>();
    prep_q<<<(B * H / 2 + 255) / 256, 256>>>(q);
    mm_tc<<<KQ / MROWS, TCTHREADS, SMEM_TC>>>(fq, lab_q, clu_q, lab_k, clu_k);
    minmax_k<<<1, 32>>>(topk);
    pos_part<<<dim3(16, B), 256>>>();
    pos_merge<<<B, 32>>>();
    for (int pass = 0; pass < 3; ++pass) {
        int shift = 8 + pass * 8;
        rs_hist<<<dim3(32, B), 256>>>(shift, pass & 1);
        rs_scan<<<B, 256>>>();
        rs_scatter<<<dim3(32, B), 256>>>(shift, pass & 1);
    }
    write_k<<<dim3(4, 320), 256>>>(out);
}

// round 8
// speedup vs baseline: 1.0669x; 1.0669x over previous
#include <cuda_runtime.h>
#include <cstdint>
#include <cstddef>

#define FULLMASK 0xFFFFFFFFu

// ---------------- problem constants ------------------------------------------
constexpr int B  = 32;
constexpr int H  = 768;
constexpr int KQ = 131072;

// ---------------- mma.sync matmul tiling --------------------------------------
constexpr int MROWS = 128;            // queue rows per CTA (1024 CTAs)
constexpr int NCHT  = H / 64;         // 12 chunks of 64 fp32
constexpr int TCTHREADS = 128;        // 4 warps; warp w owns rows [32w,32w+32)
constexpr int AST   = 36;             // A smem stride in words (32 + 4 pad)
// smem layout (bytes)
constexpr int SM_A     = 0;                      // hi: 128*36*4=18432, lo: +18432
constexpr int SM_B     = 36864;                  // hi: 32*36*4=4608,  lo: +4608
constexpr int SM_CLB   = 46080;                  // 32 ints
constexpr int SM_LBB   = 46208;                  // 32 ints
constexpr int SMEM_TC  = 46336;
// epilogue reuse (inside A region):
constexpr int SM_SIMS  = 0;                      // 128*33 floats = 16896
constexpr int SM_STAGE = 16896;                  // 4096 uints = 16384
constexpr int SM_WC    = 33280;                  // 256 ints
constexpr int SM_LOFS  = 34304;                  // 64 ints
constexpr int SM_BASE  = 34560;                  // 64 ints
constexpr int SM_CNT   = 34816;                  // 64 ints

// ---------------- scratch ----------------------------------------------------
__device__ unsigned int g_bufP [(size_t)B * KQ];
__device__ unsigned int g_bufN0[(size_t)B * KQ];
__device__ unsigned int g_bufN1[(size_t)B * KQ];
__device__ unsigned int g_histA[B * 8192];
__device__ int g_cntP[B];
__device__ int g_cntN[B];
__device__ int g_pmm[2];
__device__ unsigned int g_posPart[B * 16 * 10];
__device__ unsigned int g_posTop[B * 16];
__device__ unsigned int g_qhi[B * H / 2];     // bf16x2 words, [32][384]
__device__ unsigned int g_qlo[B * H / 2];

__device__ __forceinline__ unsigned int keyOf(float f) {
    unsigned int u = __float_as_uint(f);
    return (u & 0x80000000u) ? u : (~u & 0x7FFFFFFFu);
}
__device__ __forceinline__ float valOf(unsigned int d) {
    unsigned int u = (d & 0x80000000u) ? d : (~d & 0x7FFFFFFFu);
    return __uint_as_float(u);
}

__device__ __forceinline__ uint32_t smem_to_u32(const void* p) {
    uint32_t a;
    asm("{ .reg .u64 t; cvta.to.shared.u64 t, %1; cvt.u32.u64 %0, t; }" : "=r"(a) : "l"(p));
    return a;
}

#define CVT_BF16X2(res, e0, e1) \
    asm("cvt.rn.satfinite.bf16x2.f32 %0, %1, %2;" : "=r"(res) : "f"(e1), "f"(e0))

// mma.sync bf16: D(16x8,f32) += A(16x16) * B(16x8)
__device__ __forceinline__ void mma_bf16(float* d, const unsigned* a, const unsigned* b) {
    asm volatile("mma.sync.aligned.m16n8k16.row.col.f32.bf16.bf16.f32 "
                 "{%0,%1,%2,%3}, {%4,%5,%6,%7}, {%8,%9}, {%0,%1,%2,%3};"
                 : "+f"(d[0]), "+f"(d[1]), "+f"(d[2]), "+f"(d[3])
                 : "r"(a[0]), "r"(a[1]), "r"(a[2]), "r"(a[3]),
                   "r"(b[0]), "r"(b[1]));
}
__device__ __forceinline__ void ldsm_x4(unsigned* r, uint32_t addr) {
    asm volatile("ldmatrix.sync.aligned.m8n8.x4.shared.b16 {%0,%1,%2,%3}, [%4];"
                 : "=r"(r[0]), "=r"(r[1]), "=r"(r[2]), "=r"(r[3]) : "r"(addr));
}

// ---------------- kernel: zero counters + split queries into bf16 hi/lo --------
__global__ void prep_q(const float* __restrict__ q) {
    int w = blockIdx.x * 256 + threadIdx.x;
    if (w < B) { g_cntP[w] = 0; g_cntN[w] = 0; }
    if (w >= B * H / 2) return;
    float x0 = q[2 * w], x1 = q[2 * w + 1];
    unsigned int whi; CVT_BF16X2(whi, x0, x1);
    float h0 = __uint_as_float(whi << 16);
    float h1 = __uint_as_float(whi & 0xFFFF0000u);
    unsigned int wlo; CVT_BF16X2(wlo, x0 - h0, x1 - h1);
    g_qhi[w] = whi;
    g_qlo[w] = wlo;
}

// ---------------- kernel 1: mma.sync + ldmatrix matmul + mask partition --------
__global__ __launch_bounds__(TCTHREADS, 2)
void mm_tc(const float* __restrict__ fq,
           const int* __restrict__ lab_q, const int* __restrict__ clu_q,
           const int* __restrict__ lab_k, const int* __restrict__ clu_k)
{
    extern __shared__ char sm[];
    const uint32_t smb = smem_to_u32(sm);
    const int t = threadIdx.x;
    const int w = t >> 5, lane = t & 31;
    const int g = lane >> 2, c4 = lane & 3;
    const int k0 = blockIdx.x * MROWS;

    int* s_clb = (int*)(sm + SM_CLB);
    int* s_lbb = (int*)(sm + SM_LBB);
    if (t < 32) { s_clb[t] = clu_q[t]; s_lbb[t] = lab_q[t]; }

    unsigned int* smAh = (unsigned int*)(sm + SM_A);
    unsigned int* smAl = smAh + MROWS * AST;         // +18432 bytes
    unsigned int* smBh = (unsigned int*)(sm + SM_B);
    unsigned int* smBl = smBh + 32 * AST;            // +4608 bytes

    // ldmatrix per-lane base addresses
    uint32_t aAddr[2][2];   // [hl][mt]
    {
        int row = w * 32 + (lane & 7) + ((lane >> 3) & 1) * 8;
        int word = ((lane >> 4) & 1) * 4;
        #pragma unroll
        for (int mt = 0; mt < 2; mt++) {
            uint32_t off = (uint32_t)(((row + mt * 16) * AST + word) * 4);
            aAddr[0][mt] = smb + SM_A + off;
            aAddr[1][mt] = smb + SM_A + 18432u + off;   // A lo: 128*36*4
        }
    }
    uint32_t bAddr[2][2];   // [hl][ntp]
    {
        int row = (lane & 7) + ((lane >> 4) & 1) * 8;
        int word = ((lane >> 3) & 1) * 4;
        #pragma unroll
        for (int ntp = 0; ntp < 2; ntp++) {
            uint32_t off = (uint32_t)(((row + ntp * 16) * AST + word) * 4);
            bAddr[0][ntp] = smb + SM_B + off;
            bAddr[1][ntp] = smb + SM_B + 4608u + off;   // B lo: 32*36*4 (was the OOB bug)
        }
    }

    const float4* gA = (const float4*)(fq + (size_t)(k0 + t) * H);

    float4 areg[16];
    unsigned int bhr[8], blr[8];

    auto loadChunk = [&](int c) {
        const float4* p = gA + c * 16;
        #pragma unroll
        for (int ii = 0; ii < 16; ii++) areg[ii] = p[ii];
        #pragma unroll
        for (int ps = 0; ps < 8; ps++) {
            int idx = ps * TCTHREADS + t;
            int n = idx >> 5, wd = idx & 31;
            bhr[ps] = g_qhi[n * (H / 2) + c * 32 + wd];
            blr[ps] = g_qlo[n * (H / 2) + c * 32 + wd];
        }
    };
    auto storeChunk = [&]() {
        #pragma unroll
        for (int ii = 0; ii < 16; ii += 2) {
            float4 v0 = areg[ii], v1 = areg[ii + 1];
            unsigned int h0, h1, h2, h3, l0, l1, l2, l3;
            CVT_BF16X2(h0, v0.x, v0.y);
            CVT_BF16X2(h1, v0.z, v0.w);
            CVT_BF16X2(h2, v1.x, v1.y);
            CVT_BF16X2(h3, v1.z, v1.w);
            float r0 = v0.x - __uint_as_float(h0 << 16);
            float r1 = v0.y - __uint_as_float(h0 & 0xFFFF0000u);
            float r2 = v0.z - __uint_as_float(h1 << 16);
            float r3 = v0.w - __uint_as_float(h1 & 0xFFFF0000u);
            float r4 = v1.x - __uint_as_float(h2 << 16);
            float r5 = v1.y - __uint_as_float(h2 & 0xFFFF0000u);
            float r6 = v1.z - __uint_as_float(h3 << 16);
            float r7 = v1.w - __uint_as_float(h3 & 0xFFFF0000u);
            CVT_BF16X2(l0, r0, r1);
            CVT_BF16X2(l1, r2, r3);
            CVT_BF16X2(l2, r4, r5);
            CVT_BF16X2(l3, r6, r7);
            *(uint4*)&smAh[t * AST + 2 * ii] = make_uint4(h0, h1, h2, h3);
            *(uint4*)&smAl[t * AST + 2 * ii] = make_uint4(l0, l1, l2, l3);
        }
        #pragma unroll
        for (int ps = 0; ps < 8; ps++) {
            int idx = ps * TCTHREADS + t;
            int n = idx >> 5, wd = idx & 31;
            smBh[n * AST + wd] = bhr[ps];
            smBl[n * AST + wd] = blr[ps];
        }
    };

    float acc[2][4][4];
    #pragma unroll
    for (int mt = 0; mt < 2; mt++)
        #pragma unroll
        for (int nt = 0; nt < 4; nt++)
            #pragma unroll
            for (int r = 0; r < 4; r++) acc[mt][nt][r] = 0.0f;

    loadChunk(0);
    for (int c = 0; c < NCHT; c++) {
        if (c > 0) __syncthreads();
        storeChunk();
        if (c + 1 < NCHT) loadChunk(c + 1);
        __syncthreads();

        #pragma unroll
        for (int ks = 0; ks < 4; ks++) {
            const uint32_t kb = (uint32_t)(ks * 32);   // 8 words
            unsigned int ah[2][4], al[2][4], bh[4][2], bl[4][2];
            #pragma unroll
            for (int mt = 0; mt < 2; mt++) {
                ldsm_x4(ah[mt], aAddr[0][mt] + kb);
                ldsm_x4(al[mt], aAddr[1][mt] + kb);
            }
            #pragma unroll
            for (int ntp = 0; ntp < 2; ntp++) {
                unsigned int rh[4], rl[4];
                ldsm_x4(rh, bAddr[0][ntp] + kb);
                ldsm_x4(rl, bAddr[1][ntp] + kb);
                bh[2 * ntp][0] = rh[0]; bh[2 * ntp][1] = rh[1];
                bh[2 * ntp + 1][0] = rh[2]; bh[2 * ntp + 1][1] = rh[3];
                bl[2 * ntp][0] = rl[0]; bl[2 * ntp][1] = rl[1];
                bl[2 * ntp + 1][0] = rl[2]; bl[2 * ntp + 1][1] = rl[3];
            }
            #pragma unroll
            for (int mt = 0; mt < 2; mt++)
                #pragma unroll
                for (int nt = 0; nt < 4; nt++)
                    mma_bf16(acc[mt][nt], ah[mt], bh[nt]);
            #pragma unroll
            for (int mt = 0; mt < 2; mt++)
                #pragma unroll
                for (int nt = 0; nt < 4; nt++)
                    mma_bf16(acc[mt][nt], ah[mt], bl[nt]);
            #pragma unroll
            for (int mt = 0; mt < 2; mt++)
                #pragma unroll
                for (int nt = 0; nt < 4; nt++)
                    mma_bf16(acc[mt][nt], al[mt], bh[nt]);
        }
    }
    __syncthreads();

    // ---- write sims fragments to smem [row][33] ------------------------------
    float* sims = (float*)(sm + SM_SIMS);
    #pragma unroll
    for (int mt = 0; mt < 2; mt++) {
        int r0 = w * 32 + mt * 16 + g;
        #pragma unroll
        for (int nt = 0; nt < 4; nt++) {
            int cb = nt * 8 + 2 * c4;
            sims[r0 * 33 + cb]           = acc[mt][nt][0];
            sims[r0 * 33 + cb + 1]       = acc[mt][nt][1];
            sims[(r0 + 8) * 33 + cb]     = acc[mt][nt][2];
            sims[(r0 + 8) * 33 + cb + 1] = acc[mt][nt][3];
        }
    }
    __syncthreads();

    // ---- epilogue: one thread per queue row ----------------------------------
    unsigned int* stage = (unsigned int*)(sm + SM_STAGE);
    int* s_wc   = (int*)(sm + SM_WC);
    int* s_lofs = (int*)(sm + SM_LOFS);
    int* s_base = (int*)(sm + SM_BASE);
    int* s_cnt  = (int*)(sm + SM_CNT);

    int clk = clu_k[k0 + t];
    int lbk = lab_k[k0 + t];
    float myS[32];
    #pragma unroll
    for (int b = 0; b < 32; b++) myS[b] = sims[t * 33 + b];

    #pragma unroll
    for (int b = 0; b < 32; b++) {
        int neg = (clk == s_clb[b]) != (lbk == s_lbb[b]);
        unsigned int mask = __ballot_sync(FULLMASK, neg);
        if (lane == 0) {
            int cn = __popc(mask);
            s_wc[(b * 2 + 1) * 4 + w] = cn;
            s_wc[(b * 2) * 4 + w] = 32 - cn;
        }
    }
    __syncthreads();
    if (t < 64) {
        int run = 0, st[4];
        #pragma unroll
        for (int ww = 0; ww < 4; ww++) { st[ww] = run; run += s_wc[t * 4 + ww]; }
        #pragma unroll
        for (int ww = 0; ww < 4; ww++) s_wc[t * 4 + ww] = st[ww];
        s_cnt[t] = run;
        int b = t >> 1, neg = t & 1;
        s_base[t] = run ? atomicAdd(neg ? &g_cntN[b] : &g_cntP[b], run) : 0;
    }
    __syncthreads();
    if (t == 0) {
        int run = 0;
        for (int s = 0; s < 64; s++) { s_lofs[s] = run; run += s_cnt[s]; }
    }
    __syncthreads();
    {
        unsigned int below = (1u << lane) - 1u;
        #pragma unroll
        for (int b = 0; b < 32; b++) {
            int neg = (clk == s_clb[b]) != (lbk == s_lbb[b]);
            unsigned int mask = __ballot_sync(FULLMASK, neg);
            int seg = b * 2 + neg;
            int rank = neg ? __popc(mask & below) : __popc(~mask & below);
            stage[s_lofs[seg] + s_wc[seg * 4 + w] + rank] = keyOf(myS[b]);
        }
    }
    __syncthreads();
    for (int s = w * 16; s < w * 16 + 16; s++) {
        int cnt = s_cnt[s];
        int b = s >> 1, neg = s & 1;
        unsigned int* dst = (neg ? g_bufN0 : g_bufP) + (size_t)b * KQ + s_base[s];
        const unsigned int* srcP = stage + s_lofs[s];
        for (int i = lane; i < cnt; i += 32) dst[i] = srcP[i];
    }
}

// ---------------- kernel 2: pos_min / neg_min ---------------------------------
__global__ void minmax_k(const int* __restrict__ topk) {
    int t = threadIdx.x;
    int cp = g_cntP[t], cn = g_cntN[t];
    #pragma unroll
    for (int off = 16; off; off >>= 1) {
        cp = min(cp, __shfl_down_sync(FULLMASK, cp, off));
        cn = min(cn, __shfl_down_sync(FULLMASK, cn, off));
    }
    if (t == 0) { g_pmm[0] = min(cp, topk[0]); g_pmm[1] = cn; }
}

// ---------------- top-10 of positives -----------------------------------------
__device__ __forceinline__ void insert10(unsigned int (&best)[10], unsigned int k) {
    if (k < best[9]) {
        int j = 9;
        #pragma unroll
        for (int s = 0; s < 9; s++) {
            if (j > 0 && best[j - 1] > k) { best[j] = best[j - 1]; j--; }
        }
        best[j] = k;
    }
}

__global__ void pos_part() {
    int c = blockIdx.x, row = blockIdx.y;
    int n = g_cntP[row];
    int per = (n + 15) >> 4;
    int s = c * per, e = min(s + per, n);
    const unsigned int* src = g_bufP + (size_t)row * KQ;
    int t = threadIdx.x;
    int w = t >> 5, lane = t & 31;
    unsigned int best[10];
    #pragma unroll
    for (int i = 0; i < 10; i++) best[i] = 0xFFFFFFFFu;
    for (int base = s; base < e; base += 1024) {
        unsigned int k0 = (base + 0 * 256 + t < e) ? src[base + 0 * 256 + t] : 0xFFFFFFFFu;
        unsigned int k1 = (base + 1 * 256 + t < e) ? src[base + 1 * 256 + t] : 0xFFFFFFFFu;
        unsigned int k2 = (base + 2 * 256 + t < e) ? src[base + 2 * 256 + t] : 0xFFFFFFFFu;
        unsigned int k3 = (base + 3 * 256 + t < e) ? src[base + 3 * 256 + t] : 0xFFFFFFFFu;
        insert10(best, k0); insert10(best, k1); insert10(best, k2); insert10(best, k3);
    }
    __shared__ unsigned int sh[8 * 10];
    #pragma unroll
    for (int r = 0; r < 10; r++) {
        unsigned int cand = best[0];
        unsigned int wmin = cand;
        #pragma unroll
        for (int off = 16; off; off >>= 1)
            wmin = min(wmin, __shfl_xor_sync(FULLMASK, wmin, off));
        unsigned int bal = __ballot_sync(FULLMASK, cand == wmin);
        int leader = __ffs(bal) - 1;
        if (lane == leader) {
            #pragma unroll
            for (int i = 0; i < 9; i++) best[i] = best[i + 1];
            best[9] = 0xFFFFFFFFu;
        }
        if (lane == 0) sh[w * 10 + r] = wmin;
    }
    __syncthreads();
    if (w == 0) {
        int head = 0;
        for (int r = 0; r < 10; r++) {
            unsigned int cand = (lane < 8) ? sh[lane * 10 + head] : 0xFFFFFFFFu;
            unsigned int wmin = cand;
            #pragma unroll
            for (int off = 16; off; off >>= 1)
                wmin = min(wmin, __shfl_xor_sync(FULLMASK, wmin, off));
            unsigned int bal = __ballot_sync(FULLMASK, cand == wmin && lane < 8);
            int leader = __ffs(bal) - 1;
            if (lane == leader) head++;
            if (lane == 0) g_posPart[(row * 16 + c) * 10 + r] = wmin;
        }
    }
}

__global__ void pos_merge() {
    int row = blockIdx.x;
    int lane = threadIdx.x;
    unsigned int v[5];
    #pragma unroll
    for (int j = 0; j < 5; j++) v[j] = g_posPart[row * 160 + lane * 5 + j];
    for (int i = 0; i < 10; i++) {
        unsigned int lmin = v[0];
        #pragma unroll
        for (int j = 1; j < 5; j++) lmin = min(lmin, v[j]);
        unsigned int wmin = lmin;
        #pragma unroll
        for (int off = 16; off; off >>= 1)
            wmin = min(wmin, __shfl_xor_sync(FULLMASK, wmin, off));
        unsigned int bal = __ballot_sync(FULLMASK, lmin == wmin);
        int leader = __ffs(bal) - 1;
        if (lane == leader) {
            bool done = false;
            #pragma unroll
            for (int j = 0; j < 5; j++) {
                if (!done && v[j] == wmin) { v[j] = 0xFFFFFFFFu; done = true; }
            }
        }
        if (lane == 0) g_posTop[row * 16 + i] = wmin;
    }
}

// ---------------- radix sort: 3x8-bit LSD over bits [8,32) --------------------
__global__ void rs_hist(int shift, int srcSel) {
    int chunk = blockIdx.x, row = blockIdx.y;
    int n = g_cntN[row];
    int s0 = chunk * 4096;
    __shared__ int h[256];
    int t = threadIdx.x;
    h[t] = 0;
    __syncthreads();
    if (s0 < n) {
        const unsigned int* in = (srcSel ? g_bufN1 : g_bufN0) + (size_t)row * KQ;
        int lim = min(4096, n - s0);
        for (int i = t; i < lim; i += 256)
            atomicAdd(&h[(in[s0 + i] >> shift) & 255], 1);
    }
    __syncthreads();
    g_histA[row * 8192 + t * 32 + chunk] = h[t];
}

__global__ void rs_scan() {
    int row = blockIdx.x;
    unsigned int* a = g_histA + row * 8192;
    int t = threadIdx.x;
    int v[32]; int sum = 0;
    int base = t * 32;
    #pragma unroll
    for (int i = 0; i < 32; i++) { v[i] = (int)a[base + i]; sum += v[i]; }
    __shared__ int ps[256];
    ps[t] = sum;
    __syncthreads();
    for (int off = 1; off < 256; off <<= 1) {
        int x = (t >= off) ? ps[t - off] : 0;
        __syncthreads();
        ps[t] += x;
        __syncthreads();
    }
    int run = (t > 0) ? ps[t - 1] : 0;
    #pragma unroll
    for (int i = 0; i < 32; i++) { int tmp = v[i]; a[base + i] = (unsigned)run; run += tmp; }
}

__global__ __launch_bounds__(256)
void rs_scatter(int shift, int srcSel) {
    int chunk = blockIdx.x, row = blockIdx.y;
    int n = g_cntN[row];
    int s0 = chunk * 4096;
    if (s0 >= n) return;
    const unsigned int* in  = (srcSel ? g_bufN1 : g_bufN0) + (size_t)row * KQ;
    unsigned int*       out = (srcSel ? g_bufN0 : g_bufN1) + (size_t)row * KQ;
    const unsigned int* Hb  = g_histA + row * 8192;

    __shared__ unsigned int sKeys[4096];
    __shared__ int wh[8 * 256];
    __shared__ int gb[256];
    __shared__ int lofs[256];
    __shared__ int ps[256];

    int t = threadIdx.x;
    int w = t >> 5, lane = t & 31;
    int wbase = s0 + 512 * w;

    unsigned int myKeys[16];
    #pragma unroll
    for (int j = 0; j < 16; j++) {
        int idx = wbase + 32 * j + lane;
        myKeys[j] = (idx < n) ? in[idx] : 0xFFFFFFFFu;
    }

    #pragma unroll
    for (int qq = 0; qq < 8; qq++) wh[qq * 256 + t] = 0;
    __syncthreads();

    #pragma unroll
    for (int j = 0; j < 16; j++) {
        int idx = wbase + 32 * j + lane;
        if (idx < n) atomicAdd(&wh[w * 256 + ((myKeys[j] >> shift) & 255)], 1);
    }
    __syncthreads();

    int tot = 0; int wstart[8];
    #pragma unroll
    for (int ww = 0; ww < 8; ww++) { wstart[ww] = tot; tot += wh[ww * 256 + t]; }
    ps[t] = tot;
    gb[t] = (int)Hb[t * 32 + chunk];
    __syncthreads();
    for (int off = 1; off < 256; off <<= 1) {
        int x = (t >= off) ? ps[t - off] : 0;
        __syncthreads();
        ps[t] += x;
        __syncthreads();
    }
    int lo = ps[t] - tot;
    lofs[t] = lo;
    #pragma unroll
    for (int ww = 0; ww < 8; ww++) wh[ww * 256 + t] = lo + wstart[ww];
    __syncthreads();

    #pragma unroll
    for (int j = 0; j < 16; j++) {
        int idx = wbase + 32 * j + lane;
        bool val = idx < n;
        unsigned int key = myKeys[j];
        int d = (key >> shift) & 255;
        unsigned int vm = __ballot_sync(FULLMASK, val);
        unsigned int peers = FULLMASK;
        #pragma unroll
        for (int bb = 0; bb < 8; ++bb) {
            unsigned int vote = __ballot_sync(FULLMASK, (d >> bb) & 1);
            peers &= ((d >> bb) & 1) ? vote : ~vote;
        }
        peers &= vm;
        int rank = __popc(peers & ((1u << lane) - 1u));
        int leader = peers ? (__ffs(peers) - 1) : 0;
        int basePos = 0;
        if (val && rank == 0) basePos = atomicAdd(&wh[w * 256 + d], __popc(peers));
        basePos = __shfl_sync(FULLMASK, basePos, leader);
        if (val) sKeys[basePos + rank] = key;
    }
    __syncthreads();

    int lim = min(4096, n - s0);
    for (int pos = t; pos < lim; pos += 256) {
        unsigned int key = sKeys[pos];
        int d = (key >> shift) & 255;
        out[gb[d] + (pos - lofs[d])] = key;
    }
}

// ---------------- writer (final sorted negatives in g_bufN1) -------------------
__global__ void write_k(float* __restrict__ out) {
    int r = blockIdx.y;
    unsigned int pm = (unsigned int)g_pmm[0];
    unsigned int nm = (unsigned int)g_pmm[1];
    if ((unsigned)r >= 32u * pm) return;
    unsigned int width = nm + 1u;
    unsigned int b = (unsigned)r / pm;
    unsigned int p = (unsigned)r - b * pm;
    const float invT = 1.0f / 0.07f;
    size_t rowBase = (size_t)r * width;
    const unsigned int* negRow = g_bufN1 + (size_t)b * KQ;

    unsigned int qlen = (width + 3u) >> 2;
    unsigned int c = blockIdx.x * qlen + threadIdx.x;
    unsigned int cend = min((blockIdx.x + 1u) * qlen, width);
    if (c >= cend) return;
    if (c == 0u) {
        out[rowBase] = valOf(g_posTop[b * 16 + p]) * invT;
        c += 256u;
        if (c >= cend) return;
    }
    unsigned int num = p * nm + (c - 1u);
    unsigned int qi = num / pm;
    unsigned int rem = num - qi * pm;
    unsigned int d256 = 256u / pm;
    unsigned int r256 = 256u - d256 * pm;
    while (c < cend) {
        out[rowBase + c] = valOf(negRow[qi]) * invT;
        c += 256u;
        qi += d256;
        rem += r256;
        if (rem >= pm) { rem -= pm; qi += 1u; }
    }
}

// ---------------- launcher ----------------------------------------------------
extern "C" void kernel_launch(void* const* d_in, const int* in_sizes, int n_in,
                              void* d_out, int out_size) {
    const float* q     = (const float*)d_in[0];
    const float* fq    = (const float*)d_in[1];
    const int* lab_q   = (const int*)d_in[2];
    const int* clu_q   = (const int*)d_in[3];
    const int* lab_k   = (const int*)d_in[4];
    const int* clu_k   = (const int*)d_in[5];
    const int* topk    = (const int*)d_in[6];
    float* out = (float*)d_out;

    prep_q<<<(B * H / 2 + 255) / 256, 256>>>(q);
    mm_tc<<<KQ / MROWS, TCTHREADS, SMEM_TC>>>(fq, lab_q, clu_q, lab_k, clu_k);
    minmax_k<<<1, 32>>>(topk);
    pos_part<<<dim3(16, B), 256>>>();
    pos_merge<<<B, 32>>>();
    for (int pass = 0; pass < 3; ++pass) {
        int shift = 8 + pass * 8;
        rs_hist<<<dim3(32, B), 256>>>(shift, pass & 1);
        rs_scan<<<B, 256>>>();
        rs_scatter<<<dim3(32, B), 256>>>(shift, pass & 1);
    }
    write_k<<<dim3(4, 320), 256>>>(out);
}